// round 14
// baseline (speedup 1.0000x reference)
#include <cuda_runtime.h>
#include <cuda_bf16.h>
#include <cstdint>

#define T_TOK 4096
#define D_DIM 2048
#define E_NUM 8
#define DG    256

#define BM 64
#define BK 16
#define STAGES 3
#define ROWB 32                       // smem bytes per row (no pad; XOR swizzle)
#define MATB (BM * ROWB)              // 2048 bytes per 64-row matrix tile

#define NX4  (T_TOK * D_DIM / 4)          // float4 count of x      (2M)
#define NW4  (E_NUM * DG * D_DIM / 4)     // float4 count of Wd/Wu  (1M each)

// ---------------- scratch (device globals; no runtime allocs) ----------------
__device__ uint16_t g_xh[(size_t)T_TOK * D_DIM];
__device__ uint16_t g_xl[(size_t)T_TOK * D_DIM];
__device__ uint16_t g_wdh[(size_t)E_NUM * DG * D_DIM];
__device__ uint16_t g_wdl[(size_t)E_NUM * DG * D_DIM];
__device__ uint16_t g_wuh[(size_t)E_NUM * D_DIM * DG];
__device__ uint16_t g_wul[(size_t)E_NUM * D_DIM * DG];
__device__ uint16_t g_dnh[(size_t)T_TOK * DG];
__device__ uint16_t g_dnl[(size_t)T_TOK * DG];
__device__ float  g_S2[2 * T_TOK * E_NUM];             // partial gate scores
__device__ int    g_list[E_NUM * T_TOK];
__device__ float  g_gatel[E_NUM * T_TOK];
__device__ int    g_cnt[E_NUM];
__device__ float  g_down_s[8 * T_TOK * DG];            // [t][slot][kphase4][DG]
__device__ float  g_up_s[(size_t)2 * T_TOK * D_DIM];   // [tok2][D]

// ---------------- PTX helpers (all baseline sm_80/90 PTX) ----------------
__device__ __forceinline__ uint32_t smem_u32(const void* p) {
    uint32_t a;
    asm("{ .reg .u64 t; cvta.to.shared.u64 t, %1; cvt.u32.u64 %0, t; }" : "=r"(a) : "l"(p));
    return a;
}
__device__ __forceinline__ void cpa16(uint32_t s, const void* g) {
    asm volatile("cp.async.cg.shared.global [%0], [%1], 16;" :: "r"(s), "l"(g));
}
#define CP_COMMIT() asm volatile("cp.async.commit_group;" ::: "memory")
#define CP_WAIT1()  asm volatile("cp.async.wait_group 1;" ::: "memory")

__device__ __forceinline__ void ldsm4(uint32_t* r, uint32_t addr) {
    asm volatile("ldmatrix.sync.aligned.m8n8.x4.shared.b16 {%0,%1,%2,%3}, [%4];"
                 : "=r"(r[0]), "=r"(r[1]), "=r"(r[2]), "=r"(r[3]) : "r"(addr));
}
__device__ __forceinline__ void mma16816(float* c, const uint32_t* a,
                                         uint32_t b0, uint32_t b1) {
    asm volatile(
        "mma.sync.aligned.m16n8k16.row.col.f32.bf16.bf16.f32 "
        "{%0,%1,%2,%3}, {%4,%5,%6,%7}, {%8,%9}, {%0,%1,%2,%3};"
        : "+f"(c[0]), "+f"(c[1]), "+f"(c[2]), "+f"(c[3])
        : "r"(a[0]), "r"(a[1]), "r"(a[2]), "r"(a[3]), "r"(b0), "r"(b1));
}

// ---------------- split helpers ----------------
__device__ __forceinline__ uint16_t bfr(__nv_bfloat16 h) {
    return *reinterpret_cast<uint16_t*>(&h);
}
__device__ __forceinline__ void split_store(float4 v, uint2* hi, uint2* lo, int j) {
    __nv_bfloat16 h0 = __float2bfloat16(v.x), h1 = __float2bfloat16(v.y),
                  h2 = __float2bfloat16(v.z), h3 = __float2bfloat16(v.w);
    __nv_bfloat16 l0 = __float2bfloat16(v.x - __bfloat162float(h0));
    __nv_bfloat16 l1 = __float2bfloat16(v.y - __bfloat162float(h1));
    __nv_bfloat16 l2 = __float2bfloat16(v.z - __bfloat162float(h2));
    __nv_bfloat16 l3 = __float2bfloat16(v.w - __bfloat162float(h3));
    uint2 H, L;
    H.x = (uint32_t)bfr(h0) | ((uint32_t)bfr(h1) << 16);
    H.y = (uint32_t)bfr(h2) | ((uint32_t)bfr(h3) << 16);
    L.x = (uint32_t)bfr(l0) | ((uint32_t)bfr(l1) << 16);
    L.y = (uint32_t)bfr(l2) | ((uint32_t)bfr(l3) << 16);
    hi[j] = H; lo[j] = L;
}

// ---------------- 1a/1b) weight split conversions (side stream) ---------------
__global__ void __launch_bounds__(256) conv_wd(const float4* __restrict__ wd) {
    int j0 = blockIdx.x * 1024 + threadIdx.x;
    float4 v0 = wd[j0], v1 = wd[j0 + 256], v2 = wd[j0 + 512], v3 = wd[j0 + 768];
    split_store(v0, (uint2*)g_wdh, (uint2*)g_wdl, j0);
    split_store(v1, (uint2*)g_wdh, (uint2*)g_wdl, j0 + 256);
    split_store(v2, (uint2*)g_wdh, (uint2*)g_wdl, j0 + 512);
    split_store(v3, (uint2*)g_wdh, (uint2*)g_wdl, j0 + 768);
}
__global__ void __launch_bounds__(256) conv_wu(const float4* __restrict__ wu) {
    int j0 = blockIdx.x * 1024 + threadIdx.x;
    float4 v0 = wu[j0], v1 = wu[j0 + 256], v2 = wu[j0 + 512], v3 = wu[j0 + 768];
    split_store(v0, (uint2*)g_wuh, (uint2*)g_wul, j0);
    split_store(v1, (uint2*)g_wuh, (uint2*)g_wul, j0 + 256);
    split_store(v2, (uint2*)g_wuh, (uint2*)g_wul, j0 + 512);
    split_store(v3, (uint2*)g_wuh, (uint2*)g_wul, j0 + 768);
}

// ---------------- 2) gating partial dots + fused x split ----------------------
__global__ void __launch_bounds__(256) gate_partial(const float* __restrict__ x,
                                                    const float* __restrict__ Wg) {
    __shared__ float wgs[E_NUM * 1024];
    int half = blockIdx.y;
    int t0 = blockIdx.x * 32;
    int tid = threadIdx.x;
    {
        const float4* src = (const float4*)Wg;
        float4* dst = (float4*)wgs;
        #pragma unroll
        for (int r = 0; r < 8; r++) {
            int idx = r * 256 + tid;
            int e = idx >> 8, c = idx & 255;
            dst[idx] = src[e * 512 + half * 256 + c];
        }
    }
    __syncthreads();
    int w = tid >> 5, lane = tid & 31;
    const float4* wv4 = (const float4*)wgs;
    uint2* xh2 = (uint2*)g_xh;
    uint2* xl2 = (uint2*)g_xl;
    #pragma unroll
    for (int j = 0; j < 4; j++) {
        int t = t0 + w * 4 + j;
        const float4* xr = (const float4*)(x + (size_t)t * D_DIM + half * 1024);
        int xo = t * (D_DIM / 4) + half * 256;      // uint2 index base
        float acc[E_NUM];
        #pragma unroll
        for (int e = 0; e < E_NUM; e++) acc[e] = 0.f;
        #pragma unroll
        for (int it = 0; it < 8; it++) {
            float4 xv = xr[it * 32 + lane];
            split_store(xv, xh2, xl2, xo + it * 32 + lane);   // fused x split
            #pragma unroll
            for (int e = 0; e < E_NUM; e++) {
                float4 wv = wv4[e * 256 + it * 32 + lane];
                acc[e] += xv.x * wv.x + xv.y * wv.y + xv.z * wv.z + xv.w * wv.w;
            }
        }
        #pragma unroll
        for (int e = 0; e < E_NUM; e++) {
            float p = acc[e];
            #pragma unroll
            for (int o = 16; o; o >>= 1) p += __shfl_down_sync(0xffffffffu, p, o);
            acc[e] = p;
        }
        if (lane == 0) {
            #pragma unroll
            for (int e = 0; e < E_NUM; e++)
                g_S2[(half * T_TOK + t) * E_NUM + e] = acc[e];
        }
    }
}

// ---------------- 3) top-2 + deterministic per-expert compaction ----------------
__global__ void __launch_bounds__(256) build_lists() {
    int e = blockIdx.x, tid = threadIdx.x;
    int wid = tid >> 5, lane = tid & 31;
    __shared__ int sbase;
    __shared__ int wtot[8];
    if (tid == 0) sbase = 0;
    __syncthreads();
    for (int t0 = 0; t0 < T_TOK; t0 += 256) {
        int t = t0 + tid;
        const float4* p0 = (const float4*)(g_S2 + (size_t)t * E_NUM);
        const float4* p1 = (const float4*)(g_S2 + (size_t)(T_TOK + t) * E_NUM);
        float4 a0 = p0[0], a1 = p0[1], b0v = p1[0], b1v = p1[1];
        float sv[E_NUM];
        sv[0] = a0.x + b0v.x; sv[1] = a0.y + b0v.y; sv[2] = a0.z + b0v.z; sv[3] = a0.w + b0v.w;
        sv[4] = a1.x + b1v.x; sv[5] = a1.y + b1v.y; sv[6] = a1.z + b1v.z; sv[7] = a1.w + b1v.w;
        #pragma unroll
        for (int k = 0; k < E_NUM; k++) sv[k] = 1.f / (1.f + expf(-sv[k]));
        int i0 = 0; float v0 = sv[0];
        #pragma unroll
        for (int k = 1; k < E_NUM; k++) if (sv[k] > v0) { v0 = sv[k]; i0 = k; }
        int i1 = -1; float v1 = -1.f;
        #pragma unroll
        for (int k = 0; k < E_NUM; k++) if (k != i0 && sv[k] > v1) { v1 = sv[k]; i1 = k; }

        int slot = -1; float g = 0.f;
        if (i0 == e) { slot = 0; g = v0; }
        else if (i1 == e) { slot = 1; g = v1; }
        bool flag = (slot >= 0);
        unsigned bal = __ballot_sync(0xffffffffu, flag);
        int wp = __popc(bal & ((1u << lane) - 1u));
        if (lane == 0) wtot[wid] = __popc(bal);
        __syncthreads();
        int off = 0;
        for (int i = 0; i < wid; i++) off += wtot[i];
        int tot = 0;
        for (int i = 0; i < 8; i++) tot += wtot[i];
        int base = sbase;
        if (flag) {
            int pos = base + off + wp;
            g_list[e * T_TOK + pos]  = t * 2 + slot;
            g_gatel[e * T_TOK + pos] = g;
        }
        __syncthreads();
        if (tid == 0) sbase = base + tot;
        __syncthreads();
    }
    if (tid == 0) g_cnt[e] = sbase;
}

// ---------------- 4) grouped GEMM: mma.sync bf16 x3, cp.async 3-stage ---------
// BM=64, 128 threads (4 warps 2x2, warp tile 32x32). 32B rows + XOR swizzle.
// 3 stages -> 7 CTAs/SM. Prefetch chunk c+2 into stage (cur+2)%3.
template <int BNT, int KS>
__global__ void __launch_bounds__(128, 7) moe_gemm_mma(
    const uint16_t* __restrict__ Ah, const uint16_t* __restrict__ Al, int lda,
    const uint16_t* __restrict__ Bh, const uint16_t* __restrict__ Bl,
    int K, int Nfull, float* __restrict__ outS) {
    constexpr int BMATB = BNT * ROWB;
    constexpr int STGB  = 2 * MATB + 2 * BMATB;
    constexpr int NJ    = 4;            // warp n-frags (32 cols / 8)
    constexpr int NGQ   = 2;            // B ldsm 16-row groups per warp
    extern __shared__ char smem[];
    __shared__ int   stok[BM];
    __shared__ float sgate[BM];

    int e = blockIdx.z;
    int cnt = g_cnt[e];
    int m0 = blockIdx.x * BM;
    if (m0 >= cnt) return;
    int ny = blockIdx.y / KS;
    int kp = blockIdx.y % KS;
    int nbase = ny * BNT;
    int Kc = K / KS;                    // K range per CTA
    int kbeg = kp * Kc;
    int tid = threadIdx.x;

    if (tid < BM) {
        int r = m0 + tid;
        if (r < cnt) { stok[tid] = g_list[e * T_TOK + r]; sgate[tid] = g_gatel[e * T_TOK + r]; }
        else         { stok[tid] = 0;                     sgate[tid] = 0.f; }
    }
    __syncthreads();

    // cp.async roles: 128 threads cover 64 rows x 2 k-halves per matrix
    int srow = tid >> 1, q = tid & 1;
    int tokrow = stok[srow] >> 1;
    const uint16_t* gAh = Ah + (size_t)tokrow * lda + kbeg + q * 8;
    const uint16_t* gAl = Al + (size_t)tokrow * lda + kbeg + q * 8;
    int brow = srow;
    size_t bro = ((size_t)e * Nfull + nbase + brow) * K + kbeg + q * 8;
    const uint16_t* gBh = Bh + bro;
    const uint16_t* gBl = Bl + bro;
    uint32_t smb = smem_u32(smem);
    uint32_t soA = (uint32_t)srow * ROWB + (((uint32_t)(q ^ (srow >> 2)) & 1u) << 4);
    uint32_t soB = (uint32_t)brow * ROWB + (((uint32_t)(q ^ (brow >> 2)) & 1u) << 4);

    int C = Kc / BK;
    #pragma unroll
    for (int s = 0; s < STAGES - 1; s++) {
        if (s < C) {
            uint32_t sb = smb + s * STGB;
            int k0 = s * BK;
            cpa16(sb + soA,                    gAh + k0);
            cpa16(sb + MATB + soA,             gAl + k0);
            cpa16(sb + 2 * MATB + soB,         gBh + k0);
            cpa16(sb + 2 * MATB + BMATB + soB, gBl + k0);
        }
        CP_COMMIT();
    }

    int wid = tid >> 5, lane = tid & 31;
    int wm = (wid & 1) * 32;              // 2 warps along M
    int wn = (wid >> 1) * 32;             // 2 warps along N
    uint32_t lrow = (uint32_t)(lane & 15);
    uint32_t swz = ((((uint32_t)lane >> 4) ^ ((uint32_t)lane >> 2)) & 1u) << 4;

    float acc[2][NJ][4];
    #pragma unroll
    for (int i = 0; i < 2; i++)
        #pragma unroll
        for (int j = 0; j < NJ; j++)
            #pragma unroll
            for (int v = 0; v < 4; v++) acc[i][j][v] = 0.f;

    // consume stage cycles 0,1,2; fill stage = (cur+2)%3 (prev-iteration's)
    int cur = 0;
    #pragma unroll 2
    for (int c = 0; c < C; c++) {
        CP_WAIT1();
        __syncthreads();
        uint32_t sb = smb + (uint32_t)cur * STGB;

        uint32_t ah[2][4], al[2][4], bh[NGQ][4], bl[NGQ][4];
        #pragma unroll
        for (int i = 0; i < 2; i++) {
            uint32_t a = sb + (wm + i * 16 + lrow) * ROWB + swz;
            ldsm4(ah[i], a);
            ldsm4(al[i], a + MATB);
        }
        #pragma unroll
        for (int gq = 0; gq < NGQ; gq++) {
            uint32_t a = sb + 2 * MATB + (wn + gq * 16 + lrow) * ROWB + swz;
            ldsm4(bh[gq], a);
            ldsm4(bl[gq], a + BMATB);
        }
        // 3 split terms, chains broken across (i,j)
        #pragma unroll
        for (int i = 0; i < 2; i++)
            #pragma unroll
            for (int j = 0; j < NJ; j++) {
                int gq = j >> 1, o = j & 1;
                mma16816(acc[i][j], ah[i], bh[gq][o], bh[gq][o + 2]);
            }
        #pragma unroll
        for (int i = 0; i < 2; i++)
            #pragma unroll
            for (int j = 0; j < NJ; j++) {
                int gq = j >> 1, o = j & 1;
                mma16816(acc[i][j], ah[i], bl[gq][o], bl[gq][o + 2]);
            }
        #pragma unroll
        for (int i = 0; i < 2; i++)
            #pragma unroll
            for (int j = 0; j < NJ; j++) {
                int gq = j >> 1, o = j & 1;
                mma16816(acc[i][j], al[i], bh[gq][o], bh[gq][o + 2]);
            }

        int nc = c + STAGES - 1;          // chunk c+2
        if (nc < C) {
            int fill = cur + (STAGES - 1);    // (cur+2) % 3
            if (fill >= STAGES) fill -= STAGES;
            uint32_t sb2 = smb + (uint32_t)fill * STGB;
            int k0 = nc * BK;
            cpa16(sb2 + soA,                    gAh + k0);
            cpa16(sb2 + MATB + soA,             gAl + k0);
            cpa16(sb2 + 2 * MATB + soB,         gBh + k0);
            cpa16(sb2 + 2 * MATB + BMATB + soB, gBl + k0);
        }
        CP_COMMIT();
        cur = (cur + 1 == STAGES) ? 0 : cur + 1;
    }

    // epilogue: gate-scale, exclusive (token,slot,kphase) scatter
    #pragma unroll
    for (int i = 0; i < 2; i++) {
        #pragma unroll
        for (int half = 0; half < 2; half++) {
            int mloc = wm + i * 16 + (lane >> 2) + half * 8;
            if (m0 + mloc >= cnt) continue;
            int tk2 = stok[mloc];
            float g = sgate[mloc];
            float* orow = outS + (size_t)(tk2 * KS + kp) * Nfull + nbase + wn + (lane & 3) * 2;
            #pragma unroll
            for (int j = 0; j < NJ; j++) {
                float2 v;
                v.x = g * acc[i][j][half * 2 + 0];
                v.y = g * acc[i][j][half * 2 + 1];
                *(float2*)(orow + j * 8) = v;
            }
        }
    }
}

// ---------------- 5) combine 8 down partials + split to bf16 hi/lo ------------
__global__ void __launch_bounds__(256) combine_down_split() {
    int i = blockIdx.x * 256 + threadIdx.x;   // over T_TOK*DG/4
    int t = i >> 6, c4 = i & 63;
    const float4* s = (const float4*)g_down_s;   // [8*T][64 float4]
    float4 v = make_float4(0.f, 0.f, 0.f, 0.f);
    #pragma unroll
    for (int p = 0; p < 8; p++) {
        float4 a = s[(t * 8 + p) * 64 + c4];
        v.x += a.x; v.y += a.y; v.z += a.z; v.w += a.w;
    }
    split_store(v, (uint2*)g_dnh, (uint2*)g_dnl, i);
}

// ---------------- 6) combine up slots -> output (4 float4/thread) -------------
__global__ void __launch_bounds__(256) combine_up(float* __restrict__ out) {
    int base = blockIdx.x * 1024 + threadIdx.x;   // over (T_TOK*D)/4 float4s
    #pragma unroll
    for (int u = 0; u < 4; u++) {
        int i = base + u * 256;
        int t = i >> 9, d4 = i & 511;
        const float4* a = (const float4*)(g_up_s + (size_t)t * 2 * D_DIM) + d4;
        const float4* b = (const float4*)(g_up_s + (size_t)t * 2 * D_DIM + D_DIM) + d4;
        float4 va = *a, vb = *b;
        ((float4*)out)[i] = make_float4(va.x + vb.x, va.y + vb.y, va.z + vb.z, va.w + vb.w);
    }
}

// ---------------- launcher ----------------
extern "C" void kernel_launch(void* const* d_in, const int* in_sizes, int n_in,
                              void* d_out, int out_size) {
    const float* x  = (const float*)d_in[0];
    const float* Wg = (const float*)d_in[1];
    const float* Wd = (const float*)d_in[2];
    const float* Wu = (const float*)d_in[3];
    float* out = (float*)d_out;

    constexpr int SMEM64 = STAGES * (2 * MATB + 2 * 64 * ROWB);    // 24576
    // One-time setup on the first (uncaptured, correctness) call: attributes,
    // side stream + fork/join events. No device memory is allocated here.
    static bool init_done = false;
    static cudaStream_t s2;
    static cudaEvent_t ev0, ev_wd, ev_wu;
    if (!init_done) {
        cudaFuncSetAttribute(moe_gemm_mma<64, 4>, cudaFuncAttributeMaxDynamicSharedMemorySize, SMEM64);
        cudaFuncSetAttribute(moe_gemm_mma<64, 4>, cudaFuncAttributePreferredSharedMemoryCarveout, 100);
        cudaFuncSetAttribute(moe_gemm_mma<64, 1>, cudaFuncAttributeMaxDynamicSharedMemorySize, SMEM64);
        cudaFuncSetAttribute(moe_gemm_mma<64, 1>, cudaFuncAttributePreferredSharedMemoryCarveout, 100);
        cudaStreamCreateWithFlags(&s2, cudaStreamNonBlocking);
        cudaEventCreateWithFlags(&ev0,   cudaEventDisableTiming);
        cudaEventCreateWithFlags(&ev_wd, cudaEventDisableTiming);
        cudaEventCreateWithFlags(&ev_wu, cudaEventDisableTiming);
        init_done = true;
    }

    void *p_xh, *p_xl, *p_wdh, *p_wdl, *p_wuh, *p_wul, *p_dnh, *p_dnl, *p_ds, *p_us;
    cudaGetSymbolAddress(&p_xh, g_xh);   cudaGetSymbolAddress(&p_xl, g_xl);
    cudaGetSymbolAddress(&p_wdh, g_wdh); cudaGetSymbolAddress(&p_wdl, g_wdl);
    cudaGetSymbolAddress(&p_wuh, g_wuh); cudaGetSymbolAddress(&p_wul, g_wul);
    cudaGetSymbolAddress(&p_dnh, g_dnh); cudaGetSymbolAddress(&p_dnl, g_dnl);
    cudaGetSymbolAddress(&p_ds, g_down_s); cudaGetSymbolAddress(&p_us, g_up_s);

    // fork side stream: weight conversions run concurrently with gate chain
    cudaEventRecord(ev0, 0);
    cudaStreamWaitEvent(s2, ev0, 0);
    conv_wd<<<NW4 / 1024, 256, 0, s2>>>((const float4*)Wd);
    cudaEventRecord(ev_wd, s2);
    conv_wu<<<NW4 / 1024, 256, 0, s2>>>((const float4*)Wu);
    cudaEventRecord(ev_wu, s2);

    // main stream: gate + lists (needs only x/Wg)
    gate_partial<<<dim3(T_TOK / 32, 2), 256>>>(x, Wg);   // also splits x
    build_lists<<<E_NUM, 256>>>();

    // down GEMM waits for Wd conversion
    cudaStreamWaitEvent(0, ev_wd, 0);
    moe_gemm_mma<64, 4><<<dim3(T_TOK / BM, (DG / 64) * 4, E_NUM), 128, SMEM64>>>(
        (const uint16_t*)p_xh, (const uint16_t*)p_xl, D_DIM,
        (const uint16_t*)p_wdh, (const uint16_t*)p_wdl, D_DIM, DG, (float*)p_ds);
    combine_down_split<<<(T_TOK * DG / 4) / 256, 256>>>();

    // up GEMM waits for Wu conversion (long done, hidden under down GEMM)
    cudaStreamWaitEvent(0, ev_wu, 0);
    moe_gemm_mma<64, 1><<<dim3(T_TOK / BM, D_DIM / 64, E_NUM), 128, SMEM64>>>(
        (const uint16_t*)p_dnh, (const uint16_t*)p_dnl, DG,
        (const uint16_t*)p_wuh, (const uint16_t*)p_wul, DG, D_DIM, (float*)p_us);
    combine_up<<<(T_TOK * D_DIM / 4) / 1024, 256>>>(out);
}

// round 15
// speedup vs baseline: 1.0626x; 1.0626x over previous
#include <cuda_runtime.h>
#include <cuda_bf16.h>
#include <cstdint>

#define T_TOK 4096
#define D_DIM 2048
#define E_NUM 8
#define DG    256

#define BM 64
#define BK 16
#define STAGES 3
#define ROWB 32                       // smem bytes per row (no pad; XOR swizzle)
#define MATB (BM * ROWB)              // 2048 bytes per 64-row matrix tile
#define NBLK 16                       // token blocks for compaction (256 each)

#define NX4  (T_TOK * D_DIM / 4)          // float4 count of x      (2M)
#define NW4  (E_NUM * DG * D_DIM / 4)     // float4 count of Wd/Wu  (1M each)

// ---------------- scratch (device globals; no runtime allocs) ----------------
__device__ uint16_t g_xh[(size_t)T_TOK * D_DIM];
__device__ uint16_t g_xl[(size_t)T_TOK * D_DIM];
__device__ uint16_t g_wdh[(size_t)E_NUM * DG * D_DIM];
__device__ uint16_t g_wdl[(size_t)E_NUM * DG * D_DIM];
__device__ uint16_t g_wuh[(size_t)E_NUM * D_DIM * DG];
__device__ uint16_t g_wul[(size_t)E_NUM * D_DIM * DG];
__device__ uint16_t g_dnh[(size_t)T_TOK * DG];
__device__ uint16_t g_dnl[(size_t)T_TOK * DG];
__device__ float  g_S2[2 * T_TOK * E_NUM];             // partial gate scores
__device__ int2   g_choice[T_TOK];
__device__ float2 g_gates[T_TOK];
__device__ int    g_bcnt[NBLK * E_NUM];                // per-(block,expert) counts
__device__ int    g_boff[NBLK * E_NUM];                // exclusive prefix
__device__ int    g_list[E_NUM * T_TOK];
__device__ float  g_gatel[E_NUM * T_TOK];
__device__ int    g_cnt[E_NUM];
__device__ float  g_down_s[8 * T_TOK * DG];            // [t][slot][kphase4][DG]
__device__ float  g_up_s[(size_t)2 * T_TOK * D_DIM];   // [tok2][D]

// ---------------- PTX helpers (all baseline sm_80/90 PTX) ----------------
__device__ __forceinline__ uint32_t smem_u32(const void* p) {
    uint32_t a;
    asm("{ .reg .u64 t; cvta.to.shared.u64 t, %1; cvt.u32.u64 %0, t; }" : "=r"(a) : "l"(p));
    return a;
}
__device__ __forceinline__ void cpa16(uint32_t s, const void* g) {
    asm volatile("cp.async.cg.shared.global [%0], [%1], 16;" :: "r"(s), "l"(g));
}
#define CP_COMMIT() asm volatile("cp.async.commit_group;" ::: "memory")
#define CP_WAIT1()  asm volatile("cp.async.wait_group 1;" ::: "memory")

__device__ __forceinline__ void ldsm4(uint32_t* r, uint32_t addr) {
    asm volatile("ldmatrix.sync.aligned.m8n8.x4.shared.b16 {%0,%1,%2,%3}, [%4];"
                 : "=r"(r[0]), "=r"(r[1]), "=r"(r[2]), "=r"(r[3]) : "r"(addr));
}
__device__ __forceinline__ void mma16816(float* c, const uint32_t* a,
                                         uint32_t b0, uint32_t b1) {
    asm volatile(
        "mma.sync.aligned.m16n8k16.row.col.f32.bf16.bf16.f32 "
        "{%0,%1,%2,%3}, {%4,%5,%6,%7}, {%8,%9}, {%0,%1,%2,%3};"
        : "+f"(c[0]), "+f"(c[1]), "+f"(c[2]), "+f"(c[3])
        : "r"(a[0]), "r"(a[1]), "r"(a[2]), "r"(a[3]), "r"(b0), "r"(b1));
}

// ---------------- split helpers ----------------
__device__ __forceinline__ uint16_t bfr(__nv_bfloat16 h) {
    return *reinterpret_cast<uint16_t*>(&h);
}
__device__ __forceinline__ void split_store(float4 v, uint2* hi, uint2* lo, int j) {
    __nv_bfloat16 h0 = __float2bfloat16(v.x), h1 = __float2bfloat16(v.y),
                  h2 = __float2bfloat16(v.z), h3 = __float2bfloat16(v.w);
    __nv_bfloat16 l0 = __float2bfloat16(v.x - __bfloat162float(h0));
    __nv_bfloat16 l1 = __float2bfloat16(v.y - __bfloat162float(h1));
    __nv_bfloat16 l2 = __float2bfloat16(v.z - __bfloat162float(h2));
    __nv_bfloat16 l3 = __float2bfloat16(v.w - __bfloat162float(h3));
    uint2 H, L;
    H.x = (uint32_t)bfr(h0) | ((uint32_t)bfr(h1) << 16);
    H.y = (uint32_t)bfr(h2) | ((uint32_t)bfr(h3) << 16);
    L.x = (uint32_t)bfr(l0) | ((uint32_t)bfr(l1) << 16);
    L.y = (uint32_t)bfr(l2) | ((uint32_t)bfr(l3) << 16);
    hi[j] = H; lo[j] = L;
}

// ---------------- 1a/1b) weight split conversions (side stream) ---------------
__global__ void __launch_bounds__(256) conv_wd(const float4* __restrict__ wd) {
    int j0 = blockIdx.x * 1024 + threadIdx.x;
    float4 v0 = wd[j0], v1 = wd[j0 + 256], v2 = wd[j0 + 512], v3 = wd[j0 + 768];
    split_store(v0, (uint2*)g_wdh, (uint2*)g_wdl, j0);
    split_store(v1, (uint2*)g_wdh, (uint2*)g_wdl, j0 + 256);
    split_store(v2, (uint2*)g_wdh, (uint2*)g_wdl, j0 + 512);
    split_store(v3, (uint2*)g_wdh, (uint2*)g_wdl, j0 + 768);
}
__global__ void __launch_bounds__(256) conv_wu(const float4* __restrict__ wu) {
    int j0 = blockIdx.x * 1024 + threadIdx.x;
    float4 v0 = wu[j0], v1 = wu[j0 + 256], v2 = wu[j0 + 512], v3 = wu[j0 + 768];
    split_store(v0, (uint2*)g_wuh, (uint2*)g_wul, j0);
    split_store(v1, (uint2*)g_wuh, (uint2*)g_wul, j0 + 256);
    split_store(v2, (uint2*)g_wuh, (uint2*)g_wul, j0 + 512);
    split_store(v3, (uint2*)g_wuh, (uint2*)g_wul, j0 + 768);
}

// ---------------- 2) gating partial dots + fused x split ----------------------
__global__ void __launch_bounds__(256) gate_partial(const float* __restrict__ x,
                                                    const float* __restrict__ Wg) {
    __shared__ float wgs[E_NUM * 1024];
    int half = blockIdx.y;
    int t0 = blockIdx.x * 32;
    int tid = threadIdx.x;
    {
        const float4* src = (const float4*)Wg;
        float4* dst = (float4*)wgs;
        #pragma unroll
        for (int r = 0; r < 8; r++) {
            int idx = r * 256 + tid;
            int e = idx >> 8, c = idx & 255;
            dst[idx] = src[e * 512 + half * 256 + c];
        }
    }
    __syncthreads();
    int w = tid >> 5, lane = tid & 31;
    const float4* wv4 = (const float4*)wgs;
    uint2* xh2 = (uint2*)g_xh;
    uint2* xl2 = (uint2*)g_xl;
    #pragma unroll
    for (int j = 0; j < 4; j++) {
        int t = t0 + w * 4 + j;
        const float4* xr = (const float4*)(x + (size_t)t * D_DIM + half * 1024);
        int xo = t * (D_DIM / 4) + half * 256;      // uint2 index base
        float acc[E_NUM];
        #pragma unroll
        for (int e = 0; e < E_NUM; e++) acc[e] = 0.f;
        #pragma unroll
        for (int it = 0; it < 8; it++) {
            float4 xv = xr[it * 32 + lane];
            split_store(xv, xh2, xl2, xo + it * 32 + lane);   // fused x split
            #pragma unroll
            for (int e = 0; e < E_NUM; e++) {
                float4 wv = wv4[e * 256 + it * 32 + lane];
                acc[e] += xv.x * wv.x + xv.y * wv.y + xv.z * wv.z + xv.w * wv.w;
            }
        }
        #pragma unroll
        for (int e = 0; e < E_NUM; e++) {
            float p = acc[e];
            #pragma unroll
            for (int o = 16; o; o >>= 1) p += __shfl_down_sync(0xffffffffu, p, o);
            acc[e] = p;
        }
        if (lane == 0) {
            #pragma unroll
            for (int e = 0; e < E_NUM; e++)
                g_S2[(half * T_TOK + t) * E_NUM + e] = acc[e];
        }
    }
}

// ---------------- 3a) per-token top-2 + per-(block,expert) counts -------------
__global__ void __launch_bounds__(256) scan_top2() {
    int blk = blockIdx.x, tid = threadIdx.x;
    int wid = tid >> 5, lane = tid & 31;
    int t = blk * 256 + tid;
    const float4* p0 = (const float4*)(g_S2 + (size_t)t * E_NUM);
    const float4* p1 = (const float4*)(g_S2 + (size_t)(T_TOK + t) * E_NUM);
    float4 a0 = p0[0], a1 = p0[1], b0v = p1[0], b1v = p1[1];
    float sv[E_NUM];
    sv[0] = a0.x + b0v.x; sv[1] = a0.y + b0v.y; sv[2] = a0.z + b0v.z; sv[3] = a0.w + b0v.w;
    sv[4] = a1.x + b1v.x; sv[5] = a1.y + b1v.y; sv[6] = a1.z + b1v.z; sv[7] = a1.w + b1v.w;
    #pragma unroll
    for (int k = 0; k < E_NUM; k++) sv[k] = 1.f / (1.f + expf(-sv[k]));
    int i0 = 0; float v0 = sv[0];
    #pragma unroll
    for (int k = 1; k < E_NUM; k++) if (sv[k] > v0) { v0 = sv[k]; i0 = k; }
    int i1 = -1; float v1 = -1.f;
    #pragma unroll
    for (int k = 0; k < E_NUM; k++) if (k != i0 && sv[k] > v1) { v1 = sv[k]; i1 = k; }
    g_choice[t] = make_int2(i0, i1);
    g_gates[t]  = make_float2(v0, v1);

    __shared__ int wcnt[8][E_NUM];
    #pragma unroll
    for (int e = 0; e < E_NUM; e++) {
        unsigned bal = __ballot_sync(0xffffffffu, i0 == e || i1 == e);
        if (lane == 0) wcnt[wid][e] = __popc(bal);
    }
    __syncthreads();
    if (tid < E_NUM) {
        int s = 0;
        #pragma unroll
        for (int w = 0; w < 8; w++) s += wcnt[w][tid];
        g_bcnt[blk * E_NUM + tid] = s;
    }
}

// ---------------- 3b) exclusive prefix over blocks per expert -----------------
__global__ void __launch_bounds__(32) calc_offsets() {
    int e = threadIdx.x;
    if (e >= E_NUM) return;
    int run = 0;
    #pragma unroll
    for (int b = 0; b < NBLK; b++) {
        g_boff[b * E_NUM + e] = run;
        run += g_bcnt[b * E_NUM + e];
    }
    g_cnt[e] = run;
}

// ---------------- 3c) deterministic scatter (token-ascending per expert) ------
__global__ void __launch_bounds__(256) scatter_lists() {
    int blk = blockIdx.x, tid = threadIdx.x;
    int wid = tid >> 5, lane = tid & 31;
    int t = blk * 256 + tid;
    int2 ch = g_choice[t];
    float2 gt = g_gates[t];

    __shared__ int wcnt[8][E_NUM];
    __shared__ int wbase[8][E_NUM];
    unsigned bal_e[E_NUM];
    #pragma unroll
    for (int e = 0; e < E_NUM; e++) {
        bal_e[e] = __ballot_sync(0xffffffffu, ch.x == e || ch.y == e);
        if (lane == 0) wcnt[wid][e] = __popc(bal_e[e]);
    }
    __syncthreads();
    if (tid < E_NUM) {
        int run = 0;
        #pragma unroll
        for (int w = 0; w < 8; w++) { wbase[w][tid] = run; run += wcnt[w][tid]; }
    }
    __syncthreads();

    unsigned lmask = (1u << lane) - 1u;
    #pragma unroll
    for (int e = 0; e < E_NUM; e++) {
        int slot = -1; float g = 0.f;
        if (ch.x == e) { slot = 0; g = gt.x; }
        else if (ch.y == e) { slot = 1; g = gt.y; }
        if (slot >= 0) {
            int pos = g_boff[blk * E_NUM + e] + wbase[wid][e] + __popc(bal_e[e] & lmask);
            g_list[e * T_TOK + pos]  = t * 2 + slot;
            g_gatel[e * T_TOK + pos] = g;
        }
    }
}

// ---------------- 4) grouped GEMM: mma.sync bf16 x3, cp.async 3-stage ---------
// BM=64, 128 threads (4 warps 2x2, warp tile 32x32). 32B rows + XOR swizzle.
// 3 stages -> 7 CTAs/SM. Prefetch chunk c+2 into stage (cur+2)%3.
template <int BNT, int KS>
__global__ void __launch_bounds__(128, 7) moe_gemm_mma(
    const uint16_t* __restrict__ Ah, const uint16_t* __restrict__ Al, int lda,
    const uint16_t* __restrict__ Bh, const uint16_t* __restrict__ Bl,
    int K, int Nfull, float* __restrict__ outS) {
    constexpr int BMATB = BNT * ROWB;
    constexpr int STGB  = 2 * MATB + 2 * BMATB;
    constexpr int NJ    = 4;            // warp n-frags (32 cols / 8)
    constexpr int NGQ   = 2;            // B ldsm 16-row groups per warp
    extern __shared__ char smem[];
    __shared__ int   stok[BM];
    __shared__ float sgate[BM];

    int e = blockIdx.z;
    int cnt = g_cnt[e];
    int m0 = blockIdx.x * BM;
    if (m0 >= cnt) return;
    int ny = blockIdx.y / KS;
    int kp = blockIdx.y % KS;
    int nbase = ny * BNT;
    int Kc = K / KS;                    // K range per CTA
    int kbeg = kp * Kc;
    int tid = threadIdx.x;

    if (tid < BM) {
        int r = m0 + tid;
        if (r < cnt) { stok[tid] = g_list[e * T_TOK + r]; sgate[tid] = g_gatel[e * T_TOK + r]; }
        else         { stok[tid] = 0;                     sgate[tid] = 0.f; }
    }
    __syncthreads();

    // cp.async roles: 128 threads cover 64 rows x 2 k-halves per matrix
    int srow = tid >> 1, q = tid & 1;
    int tokrow = stok[srow] >> 1;
    const uint16_t* gAh = Ah + (size_t)tokrow * lda + kbeg + q * 8;
    const uint16_t* gAl = Al + (size_t)tokrow * lda + kbeg + q * 8;
    int brow = srow;
    size_t bro = ((size_t)e * Nfull + nbase + brow) * K + kbeg + q * 8;
    const uint16_t* gBh = Bh + bro;
    const uint16_t* gBl = Bl + bro;
    uint32_t smb = smem_u32(smem);
    uint32_t soA = (uint32_t)srow * ROWB + (((uint32_t)(q ^ (srow >> 2)) & 1u) << 4);
    uint32_t soB = (uint32_t)brow * ROWB + (((uint32_t)(q ^ (brow >> 2)) & 1u) << 4);

    int C = Kc / BK;
    #pragma unroll
    for (int s = 0; s < STAGES - 1; s++) {
        if (s < C) {
            uint32_t sb = smb + s * STGB;
            int k0 = s * BK;
            cpa16(sb + soA,                    gAh + k0);
            cpa16(sb + MATB + soA,             gAl + k0);
            cpa16(sb + 2 * MATB + soB,         gBh + k0);
            cpa16(sb + 2 * MATB + BMATB + soB, gBl + k0);
        }
        CP_COMMIT();
    }

    int wid = tid >> 5, lane = tid & 31;
    int wm = (wid & 1) * 32;              // 2 warps along M
    int wn = (wid >> 1) * 32;             // 2 warps along N
    uint32_t lrow = (uint32_t)(lane & 15);
    uint32_t swz = ((((uint32_t)lane >> 4) ^ ((uint32_t)lane >> 2)) & 1u) << 4;

    float acc[2][NJ][4];
    #pragma unroll
    for (int i = 0; i < 2; i++)
        #pragma unroll
        for (int j = 0; j < NJ; j++)
            #pragma unroll
            for (int v = 0; v < 4; v++) acc[i][j][v] = 0.f;

    // consume stage cycles 0,1,2; fill stage = (cur+2)%3 (prev-iteration's)
    int cur = 0;
    #pragma unroll 2
    for (int c = 0; c < C; c++) {
        CP_WAIT1();
        __syncthreads();
        uint32_t sb = smb + (uint32_t)cur * STGB;

        uint32_t ah[2][4], al[2][4], bh[NGQ][4], bl[NGQ][4];
        #pragma unroll
        for (int i = 0; i < 2; i++) {
            uint32_t a = sb + (wm + i * 16 + lrow) * ROWB + swz;
            ldsm4(ah[i], a);
            ldsm4(al[i], a + MATB);
        }
        #pragma unroll
        for (int gq = 0; gq < NGQ; gq++) {
            uint32_t a = sb + 2 * MATB + (wn + gq * 16 + lrow) * ROWB + swz;
            ldsm4(bh[gq], a);
            ldsm4(bl[gq], a + BMATB);
        }
        // 3 split terms, chains broken across (i,j)
        #pragma unroll
        for (int i = 0; i < 2; i++)
            #pragma unroll
            for (int j = 0; j < NJ; j++) {
                int gq = j >> 1, o = j & 1;
                mma16816(acc[i][j], ah[i], bh[gq][o], bh[gq][o + 2]);
            }
        #pragma unroll
        for (int i = 0; i < 2; i++)
            #pragma unroll
            for (int j = 0; j < NJ; j++) {
                int gq = j >> 1, o = j & 1;
                mma16816(acc[i][j], ah[i], bl[gq][o], bl[gq][o + 2]);
            }
        #pragma unroll
        for (int i = 0; i < 2; i++)
            #pragma unroll
            for (int j = 0; j < NJ; j++) {
                int gq = j >> 1, o = j & 1;
                mma16816(acc[i][j], al[i], bh[gq][o], bh[gq][o + 2]);
            }

        int nc = c + STAGES - 1;          // chunk c+2
        if (nc < C) {
            int fill = cur + (STAGES - 1);    // (cur+2) % 3
            if (fill >= STAGES) fill -= STAGES;
            uint32_t sb2 = smb + (uint32_t)fill * STGB;
            int k0 = nc * BK;
            cpa16(sb2 + soA,                    gAh + k0);
            cpa16(sb2 + MATB + soA,             gAl + k0);
            cpa16(sb2 + 2 * MATB + soB,         gBh + k0);
            cpa16(sb2 + 2 * MATB + BMATB + soB, gBl + k0);
        }
        CP_COMMIT();
        cur = (cur + 1 == STAGES) ? 0 : cur + 1;
    }

    // epilogue: gate-scale, exclusive (token,slot,kphase) scatter
    #pragma unroll
    for (int i = 0; i < 2; i++) {
        #pragma unroll
        for (int half = 0; half < 2; half++) {
            int mloc = wm + i * 16 + (lane >> 2) + half * 8;
            if (m0 + mloc >= cnt) continue;
            int tk2 = stok[mloc];
            float g = sgate[mloc];
            float* orow = outS + (size_t)(tk2 * KS + kp) * Nfull + nbase + wn + (lane & 3) * 2;
            #pragma unroll
            for (int j = 0; j < NJ; j++) {
                float2 v;
                v.x = g * acc[i][j][half * 2 + 0];
                v.y = g * acc[i][j][half * 2 + 1];
                *(float2*)(orow + j * 8) = v;
            }
        }
    }
}

// ---------------- 5) combine 8 down partials + split to bf16 hi/lo ------------
__global__ void __launch_bounds__(256) combine_down_split() {
    int i = blockIdx.x * 256 + threadIdx.x;   // over T_TOK*DG/4
    int t = i >> 6, c4 = i & 63;
    const float4* s = (const float4*)g_down_s;   // [8*T][64 float4]
    float4 v = make_float4(0.f, 0.f, 0.f, 0.f);
    #pragma unroll
    for (int p = 0; p < 8; p++) {
        float4 a = s[(t * 8 + p) * 64 + c4];
        v.x += a.x; v.y += a.y; v.z += a.z; v.w += a.w;
    }
    split_store(v, (uint2*)g_dnh, (uint2*)g_dnl, i);
}

// ---------------- 6) combine up slots -> output (4 float4/thread) -------------
__global__ void __launch_bounds__(256) combine_up(float* __restrict__ out) {
    int base = blockIdx.x * 1024 + threadIdx.x;   // over (T_TOK*D)/4 float4s
    #pragma unroll
    for (int u = 0; u < 4; u++) {
        int i = base + u * 256;
        int t = i >> 9, d4 = i & 511;
        const float4* a = (const float4*)(g_up_s + (size_t)t * 2 * D_DIM) + d4;
        const float4* b = (const float4*)(g_up_s + (size_t)t * 2 * D_DIM + D_DIM) + d4;
        float4 va = *a, vb = *b;
        ((float4*)out)[i] = make_float4(va.x + vb.x, va.y + vb.y, va.z + vb.z, va.w + vb.w);
    }
}

// ---------------- launcher ----------------
extern "C" void kernel_launch(void* const* d_in, const int* in_sizes, int n_in,
                              void* d_out, int out_size) {
    const float* x  = (const float*)d_in[0];
    const float* Wg = (const float*)d_in[1];
    const float* Wd = (const float*)d_in[2];
    const float* Wu = (const float*)d_in[3];
    float* out = (float*)d_out;

    constexpr int SMEM64 = STAGES * (2 * MATB + 2 * 64 * ROWB);    // 24576
    static bool init_done = false;
    static cudaStream_t s2;
    static cudaEvent_t ev0, ev_wd, ev_wu;
    if (!init_done) {
        cudaFuncSetAttribute(moe_gemm_mma<64, 4>, cudaFuncAttributeMaxDynamicSharedMemorySize, SMEM64);
        cudaFuncSetAttribute(moe_gemm_mma<64, 4>, cudaFuncAttributePreferredSharedMemoryCarveout, 100);
        cudaFuncSetAttribute(moe_gemm_mma<64, 1>, cudaFuncAttributeMaxDynamicSharedMemorySize, SMEM64);
        cudaFuncSetAttribute(moe_gemm_mma<64, 1>, cudaFuncAttributePreferredSharedMemoryCarveout, 100);
        cudaStreamCreateWithFlags(&s2, cudaStreamNonBlocking);
        cudaEventCreateWithFlags(&ev0,   cudaEventDisableTiming);
        cudaEventCreateWithFlags(&ev_wd, cudaEventDisableTiming);
        cudaEventCreateWithFlags(&ev_wu, cudaEventDisableTiming);
        init_done = true;
    }

    void *p_xh, *p_xl, *p_wdh, *p_wdl, *p_wuh, *p_wul, *p_dnh, *p_dnl, *p_ds, *p_us;
    cudaGetSymbolAddress(&p_xh, g_xh);   cudaGetSymbolAddress(&p_xl, g_xl);
    cudaGetSymbolAddress(&p_wdh, g_wdh); cudaGetSymbolAddress(&p_wdl, g_wdl);
    cudaGetSymbolAddress(&p_wuh, g_wuh); cudaGetSymbolAddress(&p_wul, g_wul);
    cudaGetSymbolAddress(&p_dnh, g_dnh); cudaGetSymbolAddress(&p_dnl, g_dnl);
    cudaGetSymbolAddress(&p_ds, g_down_s); cudaGetSymbolAddress(&p_us, g_up_s);

    // fork side stream: weight conversions run concurrently with gate chain
    cudaEventRecord(ev0, 0);
    cudaStreamWaitEvent(s2, ev0, 0);
    conv_wd<<<NW4 / 1024, 256, 0, s2>>>((const float4*)Wd);
    cudaEventRecord(ev_wd, s2);
    conv_wu<<<NW4 / 1024, 256, 0, s2>>>((const float4*)Wu);
    cudaEventRecord(ev_wu, s2);

    // main stream: gate + parallel compaction (needs only x/Wg)
    gate_partial<<<dim3(T_TOK / 32, 2), 256>>>(x, Wg);   // also splits x
    scan_top2<<<NBLK, 256>>>();
    calc_offsets<<<1, 32>>>();
    scatter_lists<<<NBLK, 256>>>();

    // down GEMM waits for Wd conversion
    cudaStreamWaitEvent(0, ev_wd, 0);
    moe_gemm_mma<64, 4><<<dim3(T_TOK / BM, (DG / 64) * 4, E_NUM), 128, SMEM64>>>(
        (const uint16_t*)p_xh, (const uint16_t*)p_xl, D_DIM,
        (const uint16_t*)p_wdh, (const uint16_t*)p_wdl, D_DIM, DG, (float*)p_ds);
    combine_down_split<<<(T_TOK * DG / 4) / 256, 256>>>();

    // up GEMM waits for Wu conversion (long done, hidden under down GEMM)
    cudaStreamWaitEvent(0, ev_wu, 0);
    moe_gemm_mma<64, 1><<<dim3(T_TOK / BM, D_DIM / 64, E_NUM), 128, SMEM64>>>(
        (const uint16_t*)p_dnh, (const uint16_t*)p_dnl, DG,
        (const uint16_t*)p_wuh, (const uint16_t*)p_wul, DG, D_DIM, (float*)p_us);
    combine_up<<<(T_TOK * D_DIM / 4) / 1024, 256>>>(out);
}

// round 16
// speedup vs baseline: 1.0671x; 1.0043x over previous
#include <cuda_runtime.h>
#include <cuda_bf16.h>
#include <cstdint>

#define T_TOK 4096
#define D_DIM 2048
#define E_NUM 8
#define DG    256

#define BM 64
#define BK 16
#define STAGES 3
#define ROWB 32                       // smem bytes per row (no pad; XOR swizzle)
#define MATB (BM * ROWB)              // 2048 bytes per 64-row matrix tile
#define NBLK 16                       // token blocks for compaction (256 each)

#define NX4  (T_TOK * D_DIM / 4)          // float4 count of x      (2M)
#define NW4  (E_NUM * DG * D_DIM / 4)     // float4 count of Wd/Wu  (1M each)

// ---------------- scratch (device globals; no runtime allocs) ----------------
__device__ uint16_t g_xh[(size_t)T_TOK * D_DIM];
__device__ uint16_t g_xl[(size_t)T_TOK * D_DIM];
__device__ uint16_t g_wdh[(size_t)E_NUM * DG * D_DIM];
__device__ uint16_t g_wdl[(size_t)E_NUM * DG * D_DIM];
__device__ uint16_t g_wuh[(size_t)E_NUM * D_DIM * DG];
__device__ uint16_t g_wul[(size_t)E_NUM * D_DIM * DG];
__device__ uint16_t g_dnh[(size_t)T_TOK * DG];
__device__ uint16_t g_dnl[(size_t)T_TOK * DG];
__device__ float  g_S2[2 * T_TOK * E_NUM];             // partial gate scores
__device__ int2   g_choice[T_TOK];
__device__ float2 g_gates[T_TOK];
__device__ int    g_bcnt[NBLK * E_NUM];                // per-(block,expert) counts
__device__ int    g_boff[NBLK * E_NUM];                // exclusive prefix
__device__ int    g_list[E_NUM * T_TOK];
__device__ float  g_gatel[E_NUM * T_TOK];
__device__ int    g_cnt[E_NUM];
__device__ float  g_down_s[8 * T_TOK * DG];            // [t][slot][kphase4][DG]

// ---------------- PTX helpers (all baseline sm_80/90 PTX) ----------------
__device__ __forceinline__ uint32_t smem_u32(const void* p) {
    uint32_t a;
    asm("{ .reg .u64 t; cvta.to.shared.u64 t, %1; cvt.u32.u64 %0, t; }" : "=r"(a) : "l"(p));
    return a;
}
__device__ __forceinline__ void cpa16(uint32_t s, const void* g) {
    asm volatile("cp.async.cg.shared.global [%0], [%1], 16;" :: "r"(s), "l"(g));
}
#define CP_COMMIT() asm volatile("cp.async.commit_group;" ::: "memory")
#define CP_WAIT1()  asm volatile("cp.async.wait_group 1;" ::: "memory")

__device__ __forceinline__ void ldsm4(uint32_t* r, uint32_t addr) {
    asm volatile("ldmatrix.sync.aligned.m8n8.x4.shared.b16 {%0,%1,%2,%3}, [%4];"
                 : "=r"(r[0]), "=r"(r[1]), "=r"(r[2]), "=r"(r[3]) : "r"(addr));
}
__device__ __forceinline__ void mma16816(float* c, const uint32_t* a,
                                         uint32_t b0, uint32_t b1) {
    asm volatile(
        "mma.sync.aligned.m16n8k16.row.col.f32.bf16.bf16.f32 "
        "{%0,%1,%2,%3}, {%4,%5,%6,%7}, {%8,%9}, {%0,%1,%2,%3};"
        : "+f"(c[0]), "+f"(c[1]), "+f"(c[2]), "+f"(c[3])
        : "r"(a[0]), "r"(a[1]), "r"(a[2]), "r"(a[3]), "r"(b0), "r"(b1));
}

// ---------------- split helpers ----------------
__device__ __forceinline__ uint16_t bfr(__nv_bfloat16 h) {
    return *reinterpret_cast<uint16_t*>(&h);
}
__device__ __forceinline__ void split_store(float4 v, uint2* hi, uint2* lo, int j) {
    __nv_bfloat16 h0 = __float2bfloat16(v.x), h1 = __float2bfloat16(v.y),
                  h2 = __float2bfloat16(v.z), h3 = __float2bfloat16(v.w);
    __nv_bfloat16 l0 = __float2bfloat16(v.x - __bfloat162float(h0));
    __nv_bfloat16 l1 = __float2bfloat16(v.y - __bfloat162float(h1));
    __nv_bfloat16 l2 = __float2bfloat16(v.z - __bfloat162float(h2));
    __nv_bfloat16 l3 = __float2bfloat16(v.w - __bfloat162float(h3));
    uint2 H, L;
    H.x = (uint32_t)bfr(h0) | ((uint32_t)bfr(h1) << 16);
    H.y = (uint32_t)bfr(h2) | ((uint32_t)bfr(h3) << 16);
    L.x = (uint32_t)bfr(l0) | ((uint32_t)bfr(l1) << 16);
    L.y = (uint32_t)bfr(l2) | ((uint32_t)bfr(l3) << 16);
    hi[j] = H; lo[j] = L;
}

// ---------------- 0) zero the output (side stream; hidden) -------------------
__global__ void __launch_bounds__(256) zero_out(float4* __restrict__ out) {
    int i = blockIdx.x * 1024 + threadIdx.x;
    float4 z = make_float4(0.f, 0.f, 0.f, 0.f);
    out[i] = z; out[i + 256] = z; out[i + 512] = z; out[i + 768] = z;
}

// ---------------- 1a/1b) weight split conversions (side stream) ---------------
__global__ void __launch_bounds__(256) conv_wd(const float4* __restrict__ wd) {
    int j0 = blockIdx.x * 1024 + threadIdx.x;
    float4 v0 = wd[j0], v1 = wd[j0 + 256], v2 = wd[j0 + 512], v3 = wd[j0 + 768];
    split_store(v0, (uint2*)g_wdh, (uint2*)g_wdl, j0);
    split_store(v1, (uint2*)g_wdh, (uint2*)g_wdl, j0 + 256);
    split_store(v2, (uint2*)g_wdh, (uint2*)g_wdl, j0 + 512);
    split_store(v3, (uint2*)g_wdh, (uint2*)g_wdl, j0 + 768);
}
__global__ void __launch_bounds__(256) conv_wu(const float4* __restrict__ wu) {
    int j0 = blockIdx.x * 1024 + threadIdx.x;
    float4 v0 = wu[j0], v1 = wu[j0 + 256], v2 = wu[j0 + 512], v3 = wu[j0 + 768];
    split_store(v0, (uint2*)g_wuh, (uint2*)g_wul, j0);
    split_store(v1, (uint2*)g_wuh, (uint2*)g_wul, j0 + 256);
    split_store(v2, (uint2*)g_wuh, (uint2*)g_wul, j0 + 512);
    split_store(v3, (uint2*)g_wuh, (uint2*)g_wul, j0 + 768);
}

// ---------------- 2) gating partial dots + fused x split ----------------------
__global__ void __launch_bounds__(256) gate_partial(const float* __restrict__ x,
                                                    const float* __restrict__ Wg) {
    __shared__ float wgs[E_NUM * 1024];
    int half = blockIdx.y;
    int t0 = blockIdx.x * 32;
    int tid = threadIdx.x;
    {
        const float4* src = (const float4*)Wg;
        float4* dst = (float4*)wgs;
        #pragma unroll
        for (int r = 0; r < 8; r++) {
            int idx = r * 256 + tid;
            int e = idx >> 8, c = idx & 255;
            dst[idx] = src[e * 512 + half * 256 + c];
        }
    }
    __syncthreads();
    int w = tid >> 5, lane = tid & 31;
    const float4* wv4 = (const float4*)wgs;
    uint2* xh2 = (uint2*)g_xh;
    uint2* xl2 = (uint2*)g_xl;
    #pragma unroll
    for (int j = 0; j < 4; j++) {
        int t = t0 + w * 4 + j;
        const float4* xr = (const float4*)(x + (size_t)t * D_DIM + half * 1024);
        int xo = t * (D_DIM / 4) + half * 256;      // uint2 index base
        float acc[E_NUM];
        #pragma unroll
        for (int e = 0; e < E_NUM; e++) acc[e] = 0.f;
        #pragma unroll
        for (int it = 0; it < 8; it++) {
            float4 xv = xr[it * 32 + lane];
            split_store(xv, xh2, xl2, xo + it * 32 + lane);   // fused x split
            #pragma unroll
            for (int e = 0; e < E_NUM; e++) {
                float4 wv = wv4[e * 256 + it * 32 + lane];
                acc[e] += xv.x * wv.x + xv.y * wv.y + xv.z * wv.z + xv.w * wv.w;
            }
        }
        #pragma unroll
        for (int e = 0; e < E_NUM; e++) {
            float p = acc[e];
            #pragma unroll
            for (int o = 16; o; o >>= 1) p += __shfl_down_sync(0xffffffffu, p, o);
            acc[e] = p;
        }
        if (lane == 0) {
            #pragma unroll
            for (int e = 0; e < E_NUM; e++)
                g_S2[(half * T_TOK + t) * E_NUM + e] = acc[e];
        }
    }
}

// ---------------- 3a) per-token top-2 + per-(block,expert) counts -------------
__global__ void __launch_bounds__(256) scan_top2() {
    int blk = blockIdx.x, tid = threadIdx.x;
    int wid = tid >> 5, lane = tid & 31;
    int t = blk * 256 + tid;
    const float4* p0 = (const float4*)(g_S2 + (size_t)t * E_NUM);
    const float4* p1 = (const float4*)(g_S2 + (size_t)(T_TOK + t) * E_NUM);
    float4 a0 = p0[0], a1 = p0[1], b0v = p1[0], b1v = p1[1];
    float sv[E_NUM];
    sv[0] = a0.x + b0v.x; sv[1] = a0.y + b0v.y; sv[2] = a0.z + b0v.z; sv[3] = a0.w + b0v.w;
    sv[4] = a1.x + b1v.x; sv[5] = a1.y + b1v.y; sv[6] = a1.z + b1v.z; sv[7] = a1.w + b1v.w;
    #pragma unroll
    for (int k = 0; k < E_NUM; k++) sv[k] = 1.f / (1.f + expf(-sv[k]));
    int i0 = 0; float v0 = sv[0];
    #pragma unroll
    for (int k = 1; k < E_NUM; k++) if (sv[k] > v0) { v0 = sv[k]; i0 = k; }
    int i1 = -1; float v1 = -1.f;
    #pragma unroll
    for (int k = 0; k < E_NUM; k++) if (k != i0 && sv[k] > v1) { v1 = sv[k]; i1 = k; }
    g_choice[t] = make_int2(i0, i1);
    g_gates[t]  = make_float2(v0, v1);

    __shared__ int wcnt[8][E_NUM];
    #pragma unroll
    for (int e = 0; e < E_NUM; e++) {
        unsigned bal = __ballot_sync(0xffffffffu, i0 == e || i1 == e);
        if (lane == 0) wcnt[wid][e] = __popc(bal);
    }
    __syncthreads();
    if (tid < E_NUM) {
        int s = 0;
        #pragma unroll
        for (int w = 0; w < 8; w++) s += wcnt[w][tid];
        g_bcnt[blk * E_NUM + tid] = s;
    }
}

// ---------------- 3b) exclusive prefix over blocks per expert -----------------
__global__ void __launch_bounds__(32) calc_offsets() {
    int e = threadIdx.x;
    if (e >= E_NUM) return;
    int run = 0;
    #pragma unroll
    for (int b = 0; b < NBLK; b++) {
        g_boff[b * E_NUM + e] = run;
        run += g_bcnt[b * E_NUM + e];
    }
    g_cnt[e] = run;
}

// ---------------- 3c) deterministic scatter (token-ascending per expert) ------
__global__ void __launch_bounds__(256) scatter_lists() {
    int blk = blockIdx.x, tid = threadIdx.x;
    int wid = tid >> 5, lane = tid & 31;
    int t = blk * 256 + tid;
    int2 ch = g_choice[t];
    float2 gt = g_gates[t];

    __shared__ int wcnt[8][E_NUM];
    __shared__ int wbase[8][E_NUM];
    unsigned bal_e[E_NUM];
    #pragma unroll
    for (int e = 0; e < E_NUM; e++) {
        bal_e[e] = __ballot_sync(0xffffffffu, ch.x == e || ch.y == e);
        if (lane == 0) wcnt[wid][e] = __popc(bal_e[e]);
    }
    __syncthreads();
    if (tid < E_NUM) {
        int run = 0;
        #pragma unroll
        for (int w = 0; w < 8; w++) { wbase[w][tid] = run; run += wcnt[w][tid]; }
    }
    __syncthreads();

    unsigned lmask = (1u << lane) - 1u;
    #pragma unroll
    for (int e = 0; e < E_NUM; e++) {
        int slot = -1; float g = 0.f;
        if (ch.x == e) { slot = 0; g = gt.x; }
        else if (ch.y == e) { slot = 1; g = gt.y; }
        if (slot >= 0) {
            int pos = g_boff[blk * E_NUM + e] + wbase[wid][e] + __popc(bal_e[e] & lmask);
            g_list[e * T_TOK + pos]  = t * 2 + slot;
            g_gatel[e * T_TOK + pos] = g;
        }
    }
}

// ---------------- 4) grouped GEMM: mma.sync bf16 x3, cp.async 3-stage ---------
// BM=64, 128 threads (4 warps 2x2, warp tile 32x32). 32B rows + XOR swizzle.
// ATOMIC=0: exclusive (token,slot,kphase) scatter to outS rows.
// ATOMIC=1: RED.ADD gate-scaled fragments directly into out[token] (L2-resident).
template <int BNT, int KS, int ATOMIC>
__global__ void __launch_bounds__(128, 7) moe_gemm_mma(
    const uint16_t* __restrict__ Ah, const uint16_t* __restrict__ Al, int lda,
    const uint16_t* __restrict__ Bh, const uint16_t* __restrict__ Bl,
    int K, int Nfull, float* __restrict__ outS) {
    constexpr int BMATB = BNT * ROWB;
    constexpr int STGB  = 2 * MATB + 2 * BMATB;
    constexpr int NJ    = 4;            // warp n-frags (32 cols / 8)
    constexpr int NGQ   = 2;            // B ldsm 16-row groups per warp
    extern __shared__ char smem[];
    __shared__ int   stok[BM];
    __shared__ float sgate[BM];

    int e = blockIdx.z;
    int cnt = g_cnt[e];
    int m0 = blockIdx.x * BM;
    if (m0 >= cnt) return;
    int ny = blockIdx.y / KS;
    int kp = blockIdx.y % KS;
    int nbase = ny * BNT;
    int Kc = K / KS;                    // K range per CTA
    int kbeg = kp * Kc;
    int tid = threadIdx.x;

    if (tid < BM) {
        int r = m0 + tid;
        if (r < cnt) { stok[tid] = g_list[e * T_TOK + r]; sgate[tid] = g_gatel[e * T_TOK + r]; }
        else         { stok[tid] = 0;                     sgate[tid] = 0.f; }
    }
    __syncthreads();

    // cp.async roles: 128 threads cover 64 rows x 2 k-halves per matrix
    int srow = tid >> 1, q = tid & 1;
    int tokrow = stok[srow] >> 1;
    const uint16_t* gAh = Ah + (size_t)tokrow * lda + kbeg + q * 8;
    const uint16_t* gAl = Al + (size_t)tokrow * lda + kbeg + q * 8;
    int brow = srow;
    size_t bro = ((size_t)e * Nfull + nbase + brow) * K + kbeg + q * 8;
    const uint16_t* gBh = Bh + bro;
    const uint16_t* gBl = Bl + bro;
    uint32_t smb = smem_u32(smem);
    uint32_t soA = (uint32_t)srow * ROWB + (((uint32_t)(q ^ (srow >> 2)) & 1u) << 4);
    uint32_t soB = (uint32_t)brow * ROWB + (((uint32_t)(q ^ (brow >> 2)) & 1u) << 4);

    int C = Kc / BK;
    #pragma unroll
    for (int s = 0; s < STAGES - 1; s++) {
        if (s < C) {
            uint32_t sb = smb + s * STGB;
            int k0 = s * BK;
            cpa16(sb + soA,                    gAh + k0);
            cpa16(sb + MATB + soA,             gAl + k0);
            cpa16(sb + 2 * MATB + soB,         gBh + k0);
            cpa16(sb + 2 * MATB + BMATB + soB, gBl + k0);
        }
        CP_COMMIT();
    }

    int wid = tid >> 5, lane = tid & 31;
    int wm = (wid & 1) * 32;              // 2 warps along M
    int wn = (wid >> 1) * 32;             // 2 warps along N
    uint32_t lrow = (uint32_t)(lane & 15);
    uint32_t swz = ((((uint32_t)lane >> 4) ^ ((uint32_t)lane >> 2)) & 1u) << 4;

    float acc[2][NJ][4];
    #pragma unroll
    for (int i = 0; i < 2; i++)
        #pragma unroll
        for (int j = 0; j < NJ; j++)
            #pragma unroll
            for (int v = 0; v < 4; v++) acc[i][j][v] = 0.f;

    // consume stage cycles 0,1,2; fill stage = (cur+2)%3 (prev-iteration's)
    int cur = 0;
    #pragma unroll 2
    for (int c = 0; c < C; c++) {
        CP_WAIT1();
        __syncthreads();
        uint32_t sb = smb + (uint32_t)cur * STGB;

        uint32_t ah[2][4], al[2][4], bh[NGQ][4], bl[NGQ][4];
        #pragma unroll
        for (int i = 0; i < 2; i++) {
            uint32_t a = sb + (wm + i * 16 + lrow) * ROWB + swz;
            ldsm4(ah[i], a);
            ldsm4(al[i], a + MATB);
        }
        #pragma unroll
        for (int gq = 0; gq < NGQ; gq++) {
            uint32_t a = sb + 2 * MATB + (wn + gq * 16 + lrow) * ROWB + swz;
            ldsm4(bh[gq], a);
            ldsm4(bl[gq], a + BMATB);
        }
        // 3 split terms, chains broken across (i,j)
        #pragma unroll
        for (int i = 0; i < 2; i++)
            #pragma unroll
            for (int j = 0; j < NJ; j++) {
                int gq = j >> 1, o = j & 1;
                mma16816(acc[i][j], ah[i], bh[gq][o], bh[gq][o + 2]);
            }
        #pragma unroll
        for (int i = 0; i < 2; i++)
            #pragma unroll
            for (int j = 0; j < NJ; j++) {
                int gq = j >> 1, o = j & 1;
                mma16816(acc[i][j], ah[i], bl[gq][o], bl[gq][o + 2]);
            }
        #pragma unroll
        for (int i = 0; i < 2; i++)
            #pragma unroll
            for (int j = 0; j < NJ; j++) {
                int gq = j >> 1, o = j & 1;
                mma16816(acc[i][j], al[i], bh[gq][o], bh[gq][o + 2]);
            }

        int nc = c + STAGES - 1;          // chunk c+2
        if (nc < C) {
            int fill = cur + (STAGES - 1);    // (cur+2) % 3
            if (fill >= STAGES) fill -= STAGES;
            uint32_t sb2 = smb + (uint32_t)fill * STGB;
            int k0 = nc * BK;
            cpa16(sb2 + soA,                    gAh + k0);
            cpa16(sb2 + MATB + soA,             gAl + k0);
            cpa16(sb2 + 2 * MATB + soB,         gBh + k0);
            cpa16(sb2 + 2 * MATB + BMATB + soB, gBl + k0);
        }
        CP_COMMIT();
        cur = (cur + 1 == STAGES) ? 0 : cur + 1;
    }

    // epilogue: gate-scale; exclusive scatter or direct RED.ADD into out
    #pragma unroll
    for (int i = 0; i < 2; i++) {
        #pragma unroll
        for (int half = 0; half < 2; half++) {
            int mloc = wm + i * 16 + (lane >> 2) + half * 8;
            if (m0 + mloc >= cnt) continue;
            int tk2 = stok[mloc];
            float g = sgate[mloc];
            if (ATOMIC) {
                float* orow = outS + (size_t)(tk2 >> 1) * Nfull + nbase + wn + (lane & 3) * 2;
                #pragma unroll
                for (int j = 0; j < NJ; j++) {
                    atomicAdd(&orow[j * 8],     g * acc[i][j][half * 2 + 0]);
                    atomicAdd(&orow[j * 8 + 1], g * acc[i][j][half * 2 + 1]);
                }
            } else {
                float* orow = outS + (size_t)(tk2 * KS + kp) * Nfull + nbase + wn + (lane & 3) * 2;
                #pragma unroll
                for (int j = 0; j < NJ; j++) {
                    float2 v;
                    v.x = g * acc[i][j][half * 2 + 0];
                    v.y = g * acc[i][j][half * 2 + 1];
                    *(float2*)(orow + j * 8) = v;
                }
            }
        }
    }
}

// ---------------- 5) combine 8 down partials + split to bf16 hi/lo ------------
__global__ void __launch_bounds__(256) combine_down_split() {
    int i = blockIdx.x * 256 + threadIdx.x;   // over T_TOK*DG/4
    int t = i >> 6, c4 = i & 63;
    const float4* s = (const float4*)g_down_s;   // [8*T][64 float4]
    float4 v = make_float4(0.f, 0.f, 0.f, 0.f);
    #pragma unroll
    for (int p = 0; p < 8; p++) {
        float4 a = s[(t * 8 + p) * 64 + c4];
        v.x += a.x; v.y += a.y; v.z += a.z; v.w += a.w;
    }
    split_store(v, (uint2*)g_dnh, (uint2*)g_dnl, i);
}

// ---------------- launcher ----------------
extern "C" void kernel_launch(void* const* d_in, const int* in_sizes, int n_in,
                              void* d_out, int out_size) {
    const float* x  = (const float*)d_in[0];
    const float* Wg = (const float*)d_in[1];
    const float* Wd = (const float*)d_in[2];
    const float* Wu = (const float*)d_in[3];
    float* out = (float*)d_out;

    constexpr int SMEM64 = STAGES * (2 * MATB + 2 * 64 * ROWB);    // 24576
    static bool init_done = false;
    static cudaStream_t s2;
    static cudaEvent_t ev0, ev_wd, ev_z;
    if (!init_done) {
        cudaFuncSetAttribute(moe_gemm_mma<64, 4, 0>, cudaFuncAttributeMaxDynamicSharedMemorySize, SMEM64);
        cudaFuncSetAttribute(moe_gemm_mma<64, 4, 0>, cudaFuncAttributePreferredSharedMemoryCarveout, 100);
        cudaFuncSetAttribute(moe_gemm_mma<64, 1, 1>, cudaFuncAttributeMaxDynamicSharedMemorySize, SMEM64);
        cudaFuncSetAttribute(moe_gemm_mma<64, 1, 1>, cudaFuncAttributePreferredSharedMemoryCarveout, 100);
        cudaStreamCreateWithFlags(&s2, cudaStreamNonBlocking);
        cudaEventCreateWithFlags(&ev0,  cudaEventDisableTiming);
        cudaEventCreateWithFlags(&ev_wd, cudaEventDisableTiming);
        cudaEventCreateWithFlags(&ev_z, cudaEventDisableTiming);
        init_done = true;
    }

    void *p_xh, *p_xl, *p_wdh, *p_wdl, *p_wuh, *p_wul, *p_dnh, *p_dnl, *p_ds;
    cudaGetSymbolAddress(&p_xh, g_xh);   cudaGetSymbolAddress(&p_xl, g_xl);
    cudaGetSymbolAddress(&p_wdh, g_wdh); cudaGetSymbolAddress(&p_wdl, g_wdl);
    cudaGetSymbolAddress(&p_wuh, g_wuh); cudaGetSymbolAddress(&p_wul, g_wul);
    cudaGetSymbolAddress(&p_dnh, g_dnh); cudaGetSymbolAddress(&p_dnl, g_dnl);
    cudaGetSymbolAddress(&p_ds, g_down_s);

    // fork side stream: weight conversions + out zero-init, hidden under gate chain
    cudaEventRecord(ev0, 0);
    cudaStreamWaitEvent(s2, ev0, 0);
    conv_wd<<<NW4 / 1024, 256, 0, s2>>>((const float4*)Wd);
    cudaEventRecord(ev_wd, s2);
    conv_wu<<<NW4 / 1024, 256, 0, s2>>>((const float4*)Wu);
    zero_out<<<(T_TOK * D_DIM / 4) / 1024, 256, 0, s2>>>((float4*)out);
    cudaEventRecord(ev_z, s2);   // conv_wu + zero both done at this point

    // main stream: gate + parallel compaction (needs only x/Wg)
    gate_partial<<<dim3(T_TOK / 32, 2), 256>>>(x, Wg);   // also splits x
    scan_top2<<<NBLK, 256>>>();
    calc_offsets<<<1, 32>>>();
    scatter_lists<<<NBLK, 256>>>();

    // down GEMM waits for Wd conversion
    cudaStreamWaitEvent(0, ev_wd, 0);
    moe_gemm_mma<64, 4, 0><<<dim3(T_TOK / BM, (DG / 64) * 4, E_NUM), 128, SMEM64>>>(
        (const uint16_t*)p_xh, (const uint16_t*)p_xl, D_DIM,
        (const uint16_t*)p_wdh, (const uint16_t*)p_wdl, D_DIM, DG, (float*)p_ds);
    combine_down_split<<<(T_TOK * DG / 4) / 256, 256>>>();

    // up GEMM waits for Wu conversion + zeroed out; REDs straight into out
    cudaStreamWaitEvent(0, ev_z, 0);
    moe_gemm_mma<64, 1, 1><<<dim3(T_TOK / BM, D_DIM / 64, E_NUM), 128, SMEM64>>>(
        (const uint16_t*)p_dnh, (const uint16_t*)p_dnl, DG,
        (const uint16_t*)p_wuh, (const uint16_t*)p_wul, DG, D_DIM, out);
}